// round 14
// baseline (speedup 1.0000x reference)
#include <cuda_runtime.h>
#include <cuda_fp16.h>
#include <cstdint>

#define B_SZ   4096
#define D_SZ   512
#define MARGIN 0.5f
#define EPSV   1e-6f
#define BIGV   1e9f

#define NSPLIT (B_SZ / 128)                  // 32 tile rows/cols (= warp size)
#define NTILES (NSPLIT * (NSPLIT + 1) / 2)   // 528 upper-triangle tiles
#define STG    32768                         // bytes per stage (A 16K + B 16K)
#define DYN_SMEM (3 * STG)
#define NPREP  296                           // wave-1 resident CTAs (2/SM x 148)
#define CCTA   128                           // combiner CTAs (8 warps x 4 anchors)

// ---------------- device scratch (no cudaMalloc allowed) ----------------
__device__ __half Ehalf[B_SZ * D_SZ];
__device__ float  g_q[B_SZ];
__device__ float  g_p[B_SZ];
__device__ float  g_hp[NSPLIT][B_SZ];
__device__ float  g_hn[NSPLIT][B_SZ];
__device__ float  g_psum[CCTA];
__device__ float  g_pcnt[CCTA];
__device__ int    g_cnt[512];
__device__ unsigned g_prep_done;
__device__ unsigned g_tiles_done;
__device__ unsigned g_done;

// ---------------- helpers ----------------
__device__ __forceinline__ uint32_t smem_u32(const void* p) {
    uint32_t a;
    asm("{ .reg .u64 t; cvta.to.shared.u64 t, %1; cvt.u32.u64 %0, t; }" : "=r"(a) : "l"(p));
    return a;
}

#define LDMATRIX_X4(r, addr)                                                      \
    asm volatile("ldmatrix.sync.aligned.m8n8.x4.shared.b16 {%0,%1,%2,%3}, [%4];"  \
        : "=r"((r)[0]), "=r"((r)[1]), "=r"((r)[2]), "=r"((r)[3]) : "r"(addr))

#define MMA16816(D, A, b0, b1)                                                    \
    asm volatile("mma.sync.aligned.m16n8k16.row.col.f32.f16.f16.f32 "             \
        "{%0,%1,%2,%3}, {%4,%5,%6,%7}, {%8,%9}, {%0,%1,%2,%3};"                   \
        : "+f"((D)[0]), "+f"((D)[1]), "+f"((D)[2]), "+f"((D)[3])                  \
        : "r"((A)[0]), "r"((A)[1]), "r"((A)[2]), "r"((A)[3]), "r"(b0), "r"(b1))

#define CP_ASYNC16(dst, src)                                                      \
    asm volatile("cp.async.cg.shared.global [%0], [%1], 16;"                      \
        :: "r"(dst), "l"(src) : "memory")
#define CP_COMMIT() asm volatile("cp.async.commit_group;" ::: "memory")

// load one 128x64-fp16 A tile (+ B tile unless diag) into a stage (xor swizzle)
__device__ __forceinline__ void load_stage(uint32_t base, int i0, int j0,
                                           int kc, int tid, bool diag) {
    uint32_t As = base, Bs = base + 16384;
#pragma unroll
    for (int it = 0; it < 4; it++) {
        int idx = tid + it * 256;
        int r = idx >> 3, ch = idx & 7;
        uint32_t dst = As + r * 128 + ((ch ^ (r & 7)) << 4);
        const void* src = &Ehalf[(size_t)(i0 + r) * D_SZ + kc + ch * 8];
        CP_ASYNC16(dst, src);
    }
    if (!diag) {
#pragma unroll
        for (int it = 0; it < 4; it++) {
            int idx = tid + it * 256;
            int r = idx >> 3, ch = idx & 7;
            uint32_t dst = Bs + r * 128 + ((ch ^ (r & 7)) << 4);
            const void* src = &Ehalf[(size_t)(j0 + r) * D_SZ + kc + ch * 8];
            CP_ASYNC16(dst, src);
        }
    }
}

// ---------------------------------------------------------------------------
// Single kernel: prep (wave-1) + gram tile + epilogue + fused combine tail.
// ---------------------------------------------------------------------------
__global__ void __launch_bounds__(256, 2)
gemm_triplet_kernel(const float* __restrict__ E, const int* __restrict__ lab,
                    float* __restrict__ out) {
    extern __shared__ __align__(1024) char dsm[];
    __shared__ int   s_labi[128];
    __shared__ int   s_labj[128];
    __shared__ float s_qi[128];
    __shared__ float s_qj[128];
    __shared__ float hp_s[128][4];
    __shared__ float hn_s[128][4];
    __shared__ float hp_cs[128][2];
    __shared__ float hn_cs[128][2];
    __shared__ float s_sum[8], s_cn[8];
    __shared__ int   s_last;

    const int bid  = blockIdx.x;
    const int tid  = threadIdx.x;
    const int wid  = tid >> 5, lane = tid & 31;

    // ===== Phase 0: fp32->fp16 convert + stats + label histogram (wave 1) ====
    if (bid < NPREP) {
        for (int row = bid * 8 + wid; row < B_SZ; row += NPREP * 8) {
            const float4* rp = reinterpret_cast<const float4*>(E + (size_t)row * D_SZ);
            uint2* hout = reinterpret_cast<uint2*>(Ehalf + (size_t)row * D_SZ);
            float s = 0.f, sq = 0.f;
#pragma unroll
            for (int q = 0; q < 4; q++) {
                float4 v = rp[lane + 32 * q];
                s  += v.x + v.y + v.z + v.w;
                sq += v.x * v.x + v.y * v.y + v.z * v.z + v.w * v.w;
                __half2 h0 = __floats2half2_rn(v.x, v.y);
                __half2 h1 = __floats2half2_rn(v.z, v.w);
                uint2 packed;
                packed.x = *reinterpret_cast<uint32_t*>(&h0);
                packed.y = *reinterpret_cast<uint32_t*>(&h1);
                hout[lane + 32 * q] = packed;
            }
#pragma unroll
            for (int off = 16; off > 0; off >>= 1) {
                s  += __shfl_xor_sync(0xffffffffu, s,  off);
                sq += __shfl_xor_sync(0xffffffffu, sq, off);
            }
            if (lane == 0) {
                g_q[row] = sq - 2.f * EPSV * s;
                g_p[row] = sq + 2.f * EPSV * s + (float)D_SZ * EPSV * EPSV;
                atomicAdd(&g_cnt[lab[row]], 1);
            }
        }
        __syncthreads();
        if (tid == 0) { __threadfence(); atomicAdd(&g_prep_done, 1u); }
    }
    // everyone waits for prep completion
    if (tid == 0) {
        while (atomicAdd(&g_prep_done, 0u) < NPREP) { __nanosleep(64); }
    }
    __syncthreads();
    __threadfence();

    // ===== map linear block id -> upper-triangle (ti, tj), ti <= tj =====
    int ti = 0, rem = bid;
    while (rem >= NSPLIT - ti) { rem -= NSPLIT - ti; ti++; }
    const int tj = ti + rem;
    const bool diag = (ti == tj);
    const int wr   = wid >> 2, wc = wid & 3;        // 2 x 4 warp grid
    const int i0   = ti * 128;
    const int j0   = tj * 128;
    const uint32_t smem = smem_u32(dsm);

    if (tid < 128) {
        s_labi[tid] = lab[i0 + tid];
        s_labj[tid] = lab[j0 + tid];
        s_qi[tid]   = g_q[i0 + tid];
        s_qj[tid]   = g_q[j0 + tid];
    }

    float d[4][4][4];
#pragma unroll
    for (int a = 0; a < 4; a++)
#pragma unroll
        for (int b = 0; b < 4; b++)
#pragma unroll
            for (int e = 0; e < 4; e++) d[a][b][e] = 0.f;

    load_stage(smem + 0 * STG, i0, j0, 0,  tid, diag); CP_COMMIT();
    load_stage(smem + 1 * STG, i0, j0, 64, tid, diag); CP_COMMIT();

#pragma unroll 1
    for (int c = 0; c < 8; c++) {
        if (c == 7) asm volatile("cp.async.wait_group 0;" ::: "memory");
        else        asm volatile("cp.async.wait_group 1;" ::: "memory");
        __syncthreads();
        if (c + 2 < 8) {
            load_stage(smem + ((c + 2) % 3) * STG, i0, j0, (c + 2) * 64, tid, diag);
            CP_COMMIT();
        }
        const uint32_t As = smem + (c % 3) * STG;
        const uint32_t Bs = diag ? As : (As + 16384);
#pragma unroll
        for (int ks = 0; ks < 4; ks++) {
            uint32_t a[4][4];
#pragma unroll
            for (int mt = 0; mt < 4; mt++) {
                int arow = wr * 64 + mt * 16 + (lane & 15);
                uint32_t ad = As + arow * 128 +
                              ((((ks << 1) | (lane >> 4)) ^ (arow & 7)) << 4);
                LDMATRIX_X4(a[mt], ad);
            }
#pragma unroll
            for (int np = 0; np < 2; np++) {
                int brow = wc * 32 + np * 16 + (lane & 15);
                uint32_t bd = Bs + brow * 128 +
                              ((((ks << 1) | (lane >> 4)) ^ (brow & 7)) << 4);
                uint32_t b[4];
                LDMATRIX_X4(b, bd);
#pragma unroll
                for (int mt = 0; mt < 4; mt++) {
                    MMA16816(d[mt][2 * np],     a[mt], b[0], b[2]);
                    MMA16816(d[mt][2 * np + 1], a[mt], b[1], b[3]);
                }
            }
        }
    }

    // ===== dual-sided epilogue =====
    float hpc[8], hnc[8];
#pragma unroll
    for (int k = 0; k < 8; k++) { hpc[k] = -BIGV; hnc[k] = BIGV; }

#pragma unroll
    for (int mt = 0; mt < 4; mt++) {
        int r0 = wr * 64 + mt * 16 + (lane >> 2);
        int li0 = s_labi[r0], li1 = s_labi[r0 + 8];
        float qi0 = s_qi[r0], qi1 = s_qi[r0 + 8];
        float hp0 = -BIGV, hp1 = -BIGV, hn0 = BIGV, hn1 = BIGV;
#pragma unroll
        for (int nt = 0; nt < 4; nt++) {
            int c0 = wc * 32 + nt * 8 + ((lane & 3) << 1);
            float q0 = s_qj[c0], q1 = s_qj[c0 + 1];
            int lj0 = s_labj[c0], lj1 = s_labj[c0 + 1];
            float g00 = d[mt][nt][0], g01 = d[mt][nt][1];
            float g10 = d[mt][nt][2], g11 = d[mt][nt][3];
            bool e00 = (li0 == lj0), e01 = (li0 == lj1);
            bool e10 = (li1 == lj0), e11 = (li1 == lj1);
            float m00 = fmaf(g00, -2.f, q0);
            float m01 = fmaf(g01, -2.f, q1);
            float m10 = fmaf(g10, -2.f, q0);
            float m11 = fmaf(g11, -2.f, q1);
            if (e00) hp0 = fmaxf(hp0, m00); else hn0 = fminf(hn0, m00);
            if (e01) hp0 = fmaxf(hp0, m01); else hn0 = fminf(hn0, m01);
            if (e10) hp1 = fmaxf(hp1, m10); else hn1 = fminf(hn1, m10);
            if (e11) hp1 = fmaxf(hp1, m11); else hn1 = fminf(hn1, m11);
            if (!diag) {
                float n00 = fmaf(g00, -2.f, qi0);
                float n01 = fmaf(g01, -2.f, qi0);
                float n10 = fmaf(g10, -2.f, qi1);
                float n11 = fmaf(g11, -2.f, qi1);
                int k0 = nt * 2, k1 = nt * 2 + 1;
                if (e00) hpc[k0] = fmaxf(hpc[k0], n00); else hnc[k0] = fminf(hnc[k0], n00);
                if (e10) hpc[k0] = fmaxf(hpc[k0], n10); else hnc[k0] = fminf(hnc[k0], n10);
                if (e01) hpc[k1] = fmaxf(hpc[k1], n01); else hnc[k1] = fminf(hnc[k1], n01);
                if (e11) hpc[k1] = fmaxf(hpc[k1], n11); else hnc[k1] = fminf(hnc[k1], n11);
            }
        }
#pragma unroll
        for (int off = 1; off < 4; off <<= 1) {
            hp0 = fmaxf(hp0, __shfl_xor_sync(0xffffffffu, hp0, off));
            hp1 = fmaxf(hp1, __shfl_xor_sync(0xffffffffu, hp1, off));
            hn0 = fminf(hn0, __shfl_xor_sync(0xffffffffu, hn0, off));
            hn1 = fminf(hn1, __shfl_xor_sync(0xffffffffu, hn1, off));
        }
        if ((lane & 3) == 0) {
            hp_s[r0][wc] = hp0; hp_s[r0 + 8][wc] = hp1;
            hn_s[r0][wc] = hn0; hn_s[r0 + 8][wc] = hn1;
        }
    }

    if (!diag) {
#pragma unroll
        for (int off = 4; off <= 16; off <<= 1) {
#pragma unroll
            for (int k = 0; k < 8; k++) {
                hpc[k] = fmaxf(hpc[k], __shfl_xor_sync(0xffffffffu, hpc[k], off));
                hnc[k] = fminf(hnc[k], __shfl_xor_sync(0xffffffffu, hnc[k], off));
            }
        }
        if ((lane >> 2) == 0) {
#pragma unroll
            for (int k = 0; k < 8; k++) {
                int col = wc * 32 + (k >> 1) * 8 + ((lane & 3) << 1) + (k & 1);
                hp_cs[col][wr] = hpc[k];
                hn_cs[col][wr] = hnc[k];
            }
        }
    }
    __syncthreads();
    if (tid < 128) {
        float hp = fmaxf(fmaxf(hp_s[tid][0], hp_s[tid][1]),
                         fmaxf(hp_s[tid][2], hp_s[tid][3]));
        float hn = fminf(fminf(hn_s[tid][0], hn_s[tid][1]),
                         fminf(hn_s[tid][2], hn_s[tid][3]));
        g_hp[tj][i0 + tid] = hp;
        g_hn[tj][i0 + tid] = hn;
        if (!diag) {
            float hpc2 = fmaxf(hp_cs[tid][0], hp_cs[tid][1]);
            float hnc2 = fminf(hn_cs[tid][0], hn_cs[tid][1]);
            g_hp[ti][j0 + tid] = hpc2;
            g_hn[ti][j0 + tid] = hnc2;
        }
    }

    // signal tile complete
    __threadfence();
    __syncthreads();
    if (tid == 0) atomicAdd(&g_tiles_done, 1u);

    // ===== fused combine tail: CTAs 0..127, warp per 4 anchors =====
    if (bid < CCTA) {
        if (tid == 0) {
            while (atomicAdd(&g_tiles_done, 0u) < NTILES) { __nanosleep(64); }
        }
        __syncthreads();
        __threadfence();    // acquire: all g_hp/g_hn visible

        const int gw = bid * 8 + wid;          // 0..1023
        const int a0 = gw * 4;                 // 4 contiguous anchors per warp

        // lane = split index; float4 spans the 4 anchors (coalesced)
        float4 hp4 = *reinterpret_cast<const float4*>(&g_hp[lane][a0]);
        float4 hn4 = *reinterpret_cast<const float4*>(&g_hn[lane][a0]);
#pragma unroll
        for (int off = 16; off > 0; off >>= 1) {
            hp4.x = fmaxf(hp4.x, __shfl_xor_sync(0xffffffffu, hp4.x, off));
            hp4.y = fmaxf(hp4.y, __shfl_xor_sync(0xffffffffu, hp4.y, off));
            hp4.z = fmaxf(hp4.z, __shfl_xor_sync(0xffffffffu, hp4.z, off));
            hp4.w = fmaxf(hp4.w, __shfl_xor_sync(0xffffffffu, hp4.w, off));
            hn4.x = fminf(hn4.x, __shfl_xor_sync(0xffffffffu, hn4.x, off));
            hn4.y = fminf(hn4.y, __shfl_xor_sync(0xffffffffu, hn4.y, off));
            hn4.z = fminf(hn4.z, __shfl_xor_sync(0xffffffffu, hn4.z, off));
            hn4.w = fminf(hn4.w, __shfl_xor_sync(0xffffffffu, hn4.w, off));
        }

        float lsum = 0.f, lcnt = 0.f;
        if (lane < 4) {
            float hp = (lane == 0) ? hp4.x : (lane == 1) ? hp4.y : (lane == 2) ? hp4.z : hp4.w;
            float hn = (lane == 0) ? hn4.x : (lane == 1) ? hn4.y : (lane == 2) ? hn4.z : hn4.w;
            int a = a0 + lane;
            int k = g_cnt[lab[a]];
            bool valid = (k >= 2) && (k < B_SZ);
            float p = g_p[a];
            float dp = sqrtf(fmaxf(p + hp, 0.f));
            float dn = sqrtf(fmaxf(p + hn, 0.f));
            float v = dp - dn + MARGIN;
            if (valid) { lsum = (v > 0.f) ? v : 0.f; lcnt = 1.f; }
        }
#pragma unroll
        for (int off = 1; off < 4; off <<= 1) {
            lsum += __shfl_xor_sync(0xffffffffu, lsum, off);
            lcnt += __shfl_xor_sync(0xffffffffu, lcnt, off);
        }
        if (lane == 0) { s_sum[wid] = lsum; s_cn[wid] = lcnt; }
        __syncthreads();
        if (tid == 0) {
            float bs = 0.f, bc = 0.f;
#pragma unroll
            for (int w = 0; w < 8; w++) { bs += s_sum[w]; bc += s_cn[w]; }
            g_psum[bid] = bs;
            g_pcnt[bid] = bc;
            __threadfence();
            unsigned old = atomicAdd(&g_done, 1u);
            s_last = (old == CCTA - 1) ? 1 : 0;
        }
        __syncthreads();
        if (s_last) {
            __threadfence();
            if (wid == 0) {
                float fs = 0.f, fc = 0.f;
#pragma unroll
                for (int r = 0; r < 4; r++) {
                    fs += g_psum[lane + r * 32];
                    fc += g_pcnt[lane + r * 32];
                }
#pragma unroll
                for (int off = 16; off > 0; off >>= 1) {
                    fs += __shfl_xor_sync(0xffffffffu, fs, off);
                    fc += __shfl_xor_sync(0xffffffffu, fc, off);
                }
                if (lane == 0) out[0] = (fc > 0.f) ? (fs / fc) : 0.f;
            }
            // reset scratch counters for next graph replay
            for (int i = tid; i < 512; i += 256) g_cnt[i] = 0;
            if (tid == 0) {
                g_done = 0; g_prep_done = 0; g_tiles_done = 0;
                __threadfence();
            }
        }
    }
}

// ---------------------------------------------------------------------------
extern "C" void kernel_launch(void* const* d_in, const int* in_sizes, int n_in,
                              void* d_out, int out_size) {
    const float* E   = (const float*)d_in[0];
    const int*   lab = (const int*)d_in[1];
    float*       out = (float*)d_out;
    (void)in_sizes; (void)n_in; (void)out_size;

    cudaFuncSetAttribute(gemm_triplet_kernel,
                         cudaFuncAttributeMaxDynamicSharedMemorySize, DYN_SMEM);

    gemm_triplet_kernel<<<NTILES, 256, DYN_SMEM>>>(E, lab, out);
}

// round 15
// speedup vs baseline: 1.1613x; 1.1613x over previous
#include <cuda_runtime.h>
#include <cuda_fp16.h>
#include <cstdint>

#define B_SZ   4096
#define D_SZ   512
#define MARGIN 0.5f
#define EPSV   1e-6f
#define BIGV   1e9f

#define NSPLIT (B_SZ / 128)                  // 32 tile rows/cols (= warp size)
#define NTILES (NSPLIT * (NSPLIT + 1) / 2)   // 528 upper-triangle tiles
#define STG    32768                         // bytes per stage (A 16K + B 16K)
#define DYN_SMEM (3 * STG)
#define NPREP  296                           // wave-1 resident CTAs (2/SM x 148)
#define CCTA   128                           // combiner slots (last 128 finishers)

// ---------------- device scratch (no cudaMalloc allowed) ----------------
__device__ __half Ehalf[B_SZ * D_SZ];
__device__ float  g_q[B_SZ];
__device__ float  g_p[B_SZ];
__device__ float  g_hp[NSPLIT][B_SZ];
__device__ float  g_hn[NSPLIT][B_SZ];
__device__ float  g_psum[CCTA];
__device__ float  g_pcnt[CCTA];
__device__ int    g_cnt[512];
__device__ unsigned g_prep_done;
__device__ unsigned g_tiles_done;            // also the ticket counter
__device__ unsigned g_done;

// ---------------- helpers ----------------
__device__ __forceinline__ uint32_t smem_u32(const void* p) {
    uint32_t a;
    asm("{ .reg .u64 t; cvta.to.shared.u64 t, %1; cvt.u32.u64 %0, t; }" : "=r"(a) : "l"(p));
    return a;
}

#define LDMATRIX_X4(r, addr)                                                      \
    asm volatile("ldmatrix.sync.aligned.m8n8.x4.shared.b16 {%0,%1,%2,%3}, [%4];"  \
        : "=r"((r)[0]), "=r"((r)[1]), "=r"((r)[2]), "=r"((r)[3]) : "r"(addr))

#define MMA16816(D, A, b0, b1)                                                    \
    asm volatile("mma.sync.aligned.m16n8k16.row.col.f32.f16.f16.f32 "             \
        "{%0,%1,%2,%3}, {%4,%5,%6,%7}, {%8,%9}, {%0,%1,%2,%3};"                   \
        : "+f"((D)[0]), "+f"((D)[1]), "+f"((D)[2]), "+f"((D)[3])                  \
        : "r"((A)[0]), "r"((A)[1]), "r"((A)[2]), "r"((A)[3]), "r"(b0), "r"(b1))

#define CP_ASYNC16(dst, src)                                                      \
    asm volatile("cp.async.cg.shared.global [%0], [%1], 16;"                      \
        :: "r"(dst), "l"(src) : "memory")
#define CP_COMMIT() asm volatile("cp.async.commit_group;" ::: "memory")

// load one 128x64-fp16 A tile (+ B tile unless diag) into a stage (xor swizzle)
__device__ __forceinline__ void load_stage(uint32_t base, int i0, int j0,
                                           int kc, int tid, bool diag) {
    uint32_t As = base, Bs = base + 16384;
#pragma unroll
    for (int it = 0; it < 4; it++) {
        int idx = tid + it * 256;
        int r = idx >> 3, ch = idx & 7;
        uint32_t dst = As + r * 128 + ((ch ^ (r & 7)) << 4);
        const void* src = &Ehalf[(size_t)(i0 + r) * D_SZ + kc + ch * 8];
        CP_ASYNC16(dst, src);
    }
    if (!diag) {
#pragma unroll
        for (int it = 0; it < 4; it++) {
            int idx = tid + it * 256;
            int r = idx >> 3, ch = idx & 7;
            uint32_t dst = Bs + r * 128 + ((ch ^ (r & 7)) << 4);
            const void* src = &Ehalf[(size_t)(j0 + r) * D_SZ + kc + ch * 8];
            CP_ASYNC16(dst, src);
        }
    }
}

// ---------------------------------------------------------------------------
// Single kernel: prep (wave-1) + gram tile + epilogue + ticketed combine tail.
// ---------------------------------------------------------------------------
__global__ void __launch_bounds__(256, 2)
gemm_triplet_kernel(const float* __restrict__ E, const int* __restrict__ lab,
                    float* __restrict__ out) {
    extern __shared__ __align__(1024) char dsm[];
    __shared__ int   s_labi[128];
    __shared__ int   s_labj[128];
    __shared__ float s_qi[128];
    __shared__ float s_qj[128];
    __shared__ float hp_s[128][4];
    __shared__ float hn_s[128][4];
    __shared__ float hp_cs[128][2];
    __shared__ float hn_cs[128][2];
    __shared__ float s_sum[8], s_cn[8];
    __shared__ unsigned s_ticket;
    __shared__ int   s_last;

    const int bid  = blockIdx.x;
    const int tid  = threadIdx.x;
    const int wid  = tid >> 5, lane = tid & 31;

    // ===== Phase 0: fp32->fp16 convert + stats + label histogram (wave 1) ====
    if (bid < NPREP) {
        for (int row = bid * 8 + wid; row < B_SZ; row += NPREP * 8) {
            const float4* rp = reinterpret_cast<const float4*>(E + (size_t)row * D_SZ);
            uint2* hout = reinterpret_cast<uint2*>(Ehalf + (size_t)row * D_SZ);
            float s = 0.f, sq = 0.f;
#pragma unroll
            for (int q = 0; q < 4; q++) {
                float4 v = rp[lane + 32 * q];
                s  += v.x + v.y + v.z + v.w;
                sq += v.x * v.x + v.y * v.y + v.z * v.z + v.w * v.w;
                __half2 h0 = __floats2half2_rn(v.x, v.y);
                __half2 h1 = __floats2half2_rn(v.z, v.w);
                uint2 packed;
                packed.x = *reinterpret_cast<uint32_t*>(&h0);
                packed.y = *reinterpret_cast<uint32_t*>(&h1);
                hout[lane + 32 * q] = packed;
            }
#pragma unroll
            for (int off = 16; off > 0; off >>= 1) {
                s  += __shfl_xor_sync(0xffffffffu, s,  off);
                sq += __shfl_xor_sync(0xffffffffu, sq, off);
            }
            if (lane == 0) {
                g_q[row] = sq - 2.f * EPSV * s;
                g_p[row] = sq + 2.f * EPSV * s + (float)D_SZ * EPSV * EPSV;
                atomicAdd(&g_cnt[lab[row]], 1);
            }
        }
        __syncthreads();
        if (tid == 0) { __threadfence(); atomicAdd(&g_prep_done, 1u); }
    }
    // everyone waits for prep completion
    if (tid == 0) {
        while (atomicAdd(&g_prep_done, 0u) < NPREP) { __nanosleep(64); }
    }
    __syncthreads();
    __threadfence();

    // ===== map linear block id -> upper-triangle (ti, tj), ti <= tj =====
    int ti = 0, rem = bid;
    while (rem >= NSPLIT - ti) { rem -= NSPLIT - ti; ti++; }
    const int tj = ti + rem;
    const bool diag = (ti == tj);
    const int wr   = wid >> 2, wc = wid & 3;        // 2 x 4 warp grid
    const int i0   = ti * 128;
    const int j0   = tj * 128;
    const uint32_t smem = smem_u32(dsm);

    if (tid < 128) {
        s_labi[tid] = lab[i0 + tid];
        s_labj[tid] = lab[j0 + tid];
        s_qi[tid]   = g_q[i0 + tid];
        s_qj[tid]   = g_q[j0 + tid];
    }

    float d[4][4][4];
#pragma unroll
    for (int a = 0; a < 4; a++)
#pragma unroll
        for (int b = 0; b < 4; b++)
#pragma unroll
            for (int e = 0; e < 4; e++) d[a][b][e] = 0.f;

    load_stage(smem + 0 * STG, i0, j0, 0,  tid, diag); CP_COMMIT();
    load_stage(smem + 1 * STG, i0, j0, 64, tid, diag); CP_COMMIT();

#pragma unroll 1
    for (int c = 0; c < 8; c++) {
        if (c == 7) asm volatile("cp.async.wait_group 0;" ::: "memory");
        else        asm volatile("cp.async.wait_group 1;" ::: "memory");
        __syncthreads();
        if (c + 2 < 8) {
            load_stage(smem + ((c + 2) % 3) * STG, i0, j0, (c + 2) * 64, tid, diag);
            CP_COMMIT();
        }
        const uint32_t As = smem + (c % 3) * STG;
        const uint32_t Bs = diag ? As : (As + 16384);
#pragma unroll
        for (int ks = 0; ks < 4; ks++) {
            uint32_t a[4][4];
#pragma unroll
            for (int mt = 0; mt < 4; mt++) {
                int arow = wr * 64 + mt * 16 + (lane & 15);
                uint32_t ad = As + arow * 128 +
                              ((((ks << 1) | (lane >> 4)) ^ (arow & 7)) << 4);
                LDMATRIX_X4(a[mt], ad);
            }
#pragma unroll
            for (int np = 0; np < 2; np++) {
                int brow = wc * 32 + np * 16 + (lane & 15);
                uint32_t bd = Bs + brow * 128 +
                              ((((ks << 1) | (lane >> 4)) ^ (brow & 7)) << 4);
                uint32_t b[4];
                LDMATRIX_X4(b, bd);
#pragma unroll
                for (int mt = 0; mt < 4; mt++) {
                    MMA16816(d[mt][2 * np],     a[mt], b[0], b[2]);
                    MMA16816(d[mt][2 * np + 1], a[mt], b[1], b[3]);
                }
            }
        }
    }

    // ===== dual-sided epilogue =====
    float hpc[8], hnc[8];
#pragma unroll
    for (int k = 0; k < 8; k++) { hpc[k] = -BIGV; hnc[k] = BIGV; }

#pragma unroll
    for (int mt = 0; mt < 4; mt++) {
        int r0 = wr * 64 + mt * 16 + (lane >> 2);
        int li0 = s_labi[r0], li1 = s_labi[r0 + 8];
        float qi0 = s_qi[r0], qi1 = s_qi[r0 + 8];
        float hp0 = -BIGV, hp1 = -BIGV, hn0 = BIGV, hn1 = BIGV;
#pragma unroll
        for (int nt = 0; nt < 4; nt++) {
            int c0 = wc * 32 + nt * 8 + ((lane & 3) << 1);
            float q0 = s_qj[c0], q1 = s_qj[c0 + 1];
            int lj0 = s_labj[c0], lj1 = s_labj[c0 + 1];
            float g00 = d[mt][nt][0], g01 = d[mt][nt][1];
            float g10 = d[mt][nt][2], g11 = d[mt][nt][3];
            bool e00 = (li0 == lj0), e01 = (li0 == lj1);
            bool e10 = (li1 == lj0), e11 = (li1 == lj1);
            float m00 = fmaf(g00, -2.f, q0);
            float m01 = fmaf(g01, -2.f, q1);
            float m10 = fmaf(g10, -2.f, q0);
            float m11 = fmaf(g11, -2.f, q1);
            if (e00) hp0 = fmaxf(hp0, m00); else hn0 = fminf(hn0, m00);
            if (e01) hp0 = fmaxf(hp0, m01); else hn0 = fminf(hn0, m01);
            if (e10) hp1 = fmaxf(hp1, m10); else hn1 = fminf(hn1, m10);
            if (e11) hp1 = fmaxf(hp1, m11); else hn1 = fminf(hn1, m11);
            if (!diag) {
                float n00 = fmaf(g00, -2.f, qi0);
                float n01 = fmaf(g01, -2.f, qi0);
                float n10 = fmaf(g10, -2.f, qi1);
                float n11 = fmaf(g11, -2.f, qi1);
                int k0 = nt * 2, k1 = nt * 2 + 1;
                if (e00) hpc[k0] = fmaxf(hpc[k0], n00); else hnc[k0] = fminf(hnc[k0], n00);
                if (e10) hpc[k0] = fmaxf(hpc[k0], n10); else hnc[k0] = fminf(hnc[k0], n10);
                if (e01) hpc[k1] = fmaxf(hpc[k1], n01); else hnc[k1] = fminf(hnc[k1], n01);
                if (e11) hpc[k1] = fmaxf(hpc[k1], n11); else hnc[k1] = fminf(hnc[k1], n11);
            }
        }
#pragma unroll
        for (int off = 1; off < 4; off <<= 1) {
            hp0 = fmaxf(hp0, __shfl_xor_sync(0xffffffffu, hp0, off));
            hp1 = fmaxf(hp1, __shfl_xor_sync(0xffffffffu, hp1, off));
            hn0 = fminf(hn0, __shfl_xor_sync(0xffffffffu, hn0, off));
            hn1 = fminf(hn1, __shfl_xor_sync(0xffffffffu, hn1, off));
        }
        if ((lane & 3) == 0) {
            hp_s[r0][wc] = hp0; hp_s[r0 + 8][wc] = hp1;
            hn_s[r0][wc] = hn0; hn_s[r0 + 8][wc] = hn1;
        }
    }

    if (!diag) {
#pragma unroll
        for (int off = 4; off <= 16; off <<= 1) {
#pragma unroll
            for (int k = 0; k < 8; k++) {
                hpc[k] = fmaxf(hpc[k], __shfl_xor_sync(0xffffffffu, hpc[k], off));
                hnc[k] = fminf(hnc[k], __shfl_xor_sync(0xffffffffu, hnc[k], off));
            }
        }
        if ((lane >> 2) == 0) {
#pragma unroll
            for (int k = 0; k < 8; k++) {
                int col = wc * 32 + (k >> 1) * 8 + ((lane & 3) << 1) + (k & 1);
                hp_cs[col][wr] = hpc[k];
                hn_cs[col][wr] = hnc[k];
            }
        }
    }
    __syncthreads();
    if (tid < 128) {
        float hp = fmaxf(fmaxf(hp_s[tid][0], hp_s[tid][1]),
                         fmaxf(hp_s[tid][2], hp_s[tid][3]));
        float hn = fminf(fminf(hn_s[tid][0], hn_s[tid][1]),
                         fminf(hn_s[tid][2], hn_s[tid][3]));
        g_hp[tj][i0 + tid] = hp;
        g_hn[tj][i0 + tid] = hn;
        if (!diag) {
            float hpc2 = fmaxf(hp_cs[tid][0], hp_cs[tid][1]);
            float hnc2 = fminf(hn_cs[tid][0], hn_cs[tid][1]);
            g_hp[ti][j0 + tid] = hpc2;
            g_hn[ti][j0 + tid] = hnc2;
        }
    }

    // ===== ticket: signal tile complete, pick combiners = LAST 128 finishers
    __threadfence();
    __syncthreads();
    if (tid == 0) s_ticket = atomicAdd(&g_tiles_done, 1u);
    __syncthreads();
    const unsigned ticket = s_ticket;

    if (ticket >= NTILES - CCTA) {
        const int cslot = (int)(ticket - (NTILES - CCTA));   // 0..127
        if (tid == 0) {
            while (atomicAdd(&g_tiles_done, 0u) < NTILES) { __nanosleep(32); }
        }
        __syncthreads();
        __threadfence();    // acquire: all g_hp/g_hn visible

        const int gw = cslot * 8 + wid;        // 0..1023
        const int a0 = gw * 4;                 // 4 contiguous anchors per warp

        // lane = split index; float4 spans the 4 anchors (coalesced)
        float4 hp4 = *reinterpret_cast<const float4*>(&g_hp[lane][a0]);
        float4 hn4 = *reinterpret_cast<const float4*>(&g_hn[lane][a0]);
#pragma unroll
        for (int off = 16; off > 0; off >>= 1) {
            hp4.x = fmaxf(hp4.x, __shfl_xor_sync(0xffffffffu, hp4.x, off));
            hp4.y = fmaxf(hp4.y, __shfl_xor_sync(0xffffffffu, hp4.y, off));
            hp4.z = fmaxf(hp4.z, __shfl_xor_sync(0xffffffffu, hp4.z, off));
            hp4.w = fmaxf(hp4.w, __shfl_xor_sync(0xffffffffu, hp4.w, off));
            hn4.x = fminf(hn4.x, __shfl_xor_sync(0xffffffffu, hn4.x, off));
            hn4.y = fminf(hn4.y, __shfl_xor_sync(0xffffffffu, hn4.y, off));
            hn4.z = fminf(hn4.z, __shfl_xor_sync(0xffffffffu, hn4.z, off));
            hn4.w = fminf(hn4.w, __shfl_xor_sync(0xffffffffu, hn4.w, off));
        }

        float lsum = 0.f, lcnt = 0.f;
        if (lane < 4) {
            float hp = (lane == 0) ? hp4.x : (lane == 1) ? hp4.y : (lane == 2) ? hp4.z : hp4.w;
            float hn = (lane == 0) ? hn4.x : (lane == 1) ? hn4.y : (lane == 2) ? hn4.z : hn4.w;
            int a = a0 + lane;
            int k = g_cnt[lab[a]];
            bool valid = (k >= 2) && (k < B_SZ);
            float p = g_p[a];
            float dp = sqrtf(fmaxf(p + hp, 0.f));
            float dn = sqrtf(fmaxf(p + hn, 0.f));
            float v = dp - dn + MARGIN;
            if (valid) { lsum = (v > 0.f) ? v : 0.f; lcnt = 1.f; }
        }
#pragma unroll
        for (int off = 1; off < 4; off <<= 1) {
            lsum += __shfl_xor_sync(0xffffffffu, lsum, off);
            lcnt += __shfl_xor_sync(0xffffffffu, lcnt, off);
        }
        if (lane == 0) { s_sum[wid] = lsum; s_cn[wid] = lcnt; }
        __syncthreads();
        if (tid == 0) {
            float bs = 0.f, bc = 0.f;
#pragma unroll
            for (int w = 0; w < 8; w++) { bs += s_sum[w]; bc += s_cn[w]; }
            g_psum[cslot] = bs;
            g_pcnt[cslot] = bc;
            __threadfence();
            unsigned old = atomicAdd(&g_done, 1u);
            s_last = (old == CCTA - 1) ? 1 : 0;
        }
        __syncthreads();
        if (s_last) {
            __threadfence();
            if (wid == 0) {
                float fs = 0.f, fc = 0.f;
#pragma unroll
                for (int r = 0; r < 4; r++) {
                    fs += g_psum[lane + r * 32];
                    fc += g_pcnt[lane + r * 32];
                }
#pragma unroll
                for (int off = 16; off > 0; off >>= 1) {
                    fs += __shfl_xor_sync(0xffffffffu, fs, off);
                    fc += __shfl_xor_sync(0xffffffffu, fc, off);
                }
                if (lane == 0) out[0] = (fc > 0.f) ? (fs / fc) : 0.f;
            }
            // reset scratch counters for next graph replay
            for (int i = tid; i < 512; i += 256) g_cnt[i] = 0;
            if (tid == 0) {
                g_done = 0; g_prep_done = 0; g_tiles_done = 0;
                __threadfence();
            }
        }
    }
}

// ---------------------------------------------------------------------------
extern "C" void kernel_launch(void* const* d_in, const int* in_sizes, int n_in,
                              void* d_out, int out_size) {
    const float* E   = (const float*)d_in[0];
    const int*   lab = (const int*)d_in[1];
    float*       out = (float*)d_out;
    (void)in_sizes; (void)n_in; (void)out_size;

    cudaFuncSetAttribute(gemm_triplet_kernel,
                         cudaFuncAttributeMaxDynamicSharedMemorySize, DYN_SMEM);

    gemm_triplet_kernel<<<NTILES, 256, DYN_SMEM>>>(E, lab, out);
}

// round 16
// speedup vs baseline: 1.2512x; 1.0775x over previous
#include <cuda_runtime.h>
#include <cuda_fp16.h>
#include <cstdint>

#define B_SZ   4096
#define D_SZ   512
#define MARGIN 0.5f
#define EPSV   1e-6f
#define BIGV   1e9f

#define NSPLIT (B_SZ / 128)                  // 32 tile rows/cols (= warp size)
#define NTILES (NSPLIT * (NSPLIT + 1) / 2)   // 528 upper-triangle tiles
#define STG    32768                         // bytes per stage (A 16K + B 16K)
#define DYN_SMEM (3 * STG)
#define CCTA   128                           // combine CTAs (8 warps x 4 anchors)

// ---------------- device scratch (no cudaMalloc allowed) ----------------
__device__ __half Ehalf[B_SZ * D_SZ];
__device__ float  g_q[B_SZ];
__device__ float  g_p[B_SZ];
__device__ float  g_hp[NSPLIT][B_SZ];
__device__ float  g_hn[NSPLIT][B_SZ];
__device__ float  g_psum[CCTA];
__device__ float  g_pcnt[CCTA];
__device__ int    g_cnt[512];
__device__ unsigned g_done;

// ---------------- helpers ----------------
__device__ __forceinline__ uint32_t smem_u32(const void* p) {
    uint32_t a;
    asm("{ .reg .u64 t; cvta.to.shared.u64 t, %1; cvt.u32.u64 %0, t; }" : "=r"(a) : "l"(p));
    return a;
}

#define LDMATRIX_X4(r, addr)                                                      \
    asm volatile("ldmatrix.sync.aligned.m8n8.x4.shared.b16 {%0,%1,%2,%3}, [%4];"  \
        : "=r"((r)[0]), "=r"((r)[1]), "=r"((r)[2]), "=r"((r)[3]) : "r"(addr))

#define MMA16816(D, A, b0, b1)                                                    \
    asm volatile("mma.sync.aligned.m16n8k16.row.col.f32.f16.f16.f32 "             \
        "{%0,%1,%2,%3}, {%4,%5,%6,%7}, {%8,%9}, {%0,%1,%2,%3};"                   \
        : "+f"((D)[0]), "+f"((D)[1]), "+f"((D)[2]), "+f"((D)[3])                  \
        : "r"((A)[0]), "r"((A)[1]), "r"((A)[2]), "r"((A)[3]), "r"(b0), "r"(b1))

#define CP_ASYNC16(dst, src)                                                      \
    asm volatile("cp.async.cg.shared.global [%0], [%1], 16;"                      \
        :: "r"(dst), "l"(src) : "memory")
#define CP_COMMIT() asm volatile("cp.async.commit_group;" ::: "memory")

// load one 128x64-fp16 A tile (+ B tile unless diag) into a stage (xor swizzle)
// 128 threads: 8 chunks of 16B each per tile side.
__device__ __forceinline__ void load_stage(uint32_t base, int i0, int j0,
                                           int kc, int tid, bool diag) {
    uint32_t As = base, Bs = base + 16384;
#pragma unroll
    for (int it = 0; it < 8; it++) {
        int idx = tid + it * 128;
        int r = idx >> 3, ch = idx & 7;
        uint32_t dst = As + r * 128 + ((ch ^ (r & 7)) << 4);
        const void* src = &Ehalf[(size_t)(i0 + r) * D_SZ + kc + ch * 8];
        CP_ASYNC16(dst, src);
    }
    if (!diag) {
#pragma unroll
        for (int it = 0; it < 8; it++) {
            int idx = tid + it * 128;
            int r = idx >> 3, ch = idx & 7;
            uint32_t dst = Bs + r * 128 + ((ch ^ (r & 7)) << 4);
            const void* src = &Ehalf[(size_t)(j0 + r) * D_SZ + kc + ch * 8];
            CP_ASYNC16(dst, src);
        }
    }
}

// ---------------------------------------------------------------------------
// Kernel 1: fp32->fp16 convert + per-row stats + label histogram.
// One warp per row, 512 blocks.
// ---------------------------------------------------------------------------
__global__ void prep_stats_kernel(const float* __restrict__ E,
                                  const int* __restrict__ lab) {
    int warp = (blockIdx.x * blockDim.x + threadIdx.x) >> 5;
    int lane = threadIdx.x & 31;
    const float4* row = reinterpret_cast<const float4*>(E + (size_t)warp * D_SZ);
    uint2* hout = reinterpret_cast<uint2*>(Ehalf + (size_t)warp * D_SZ);
    float s = 0.f, sq = 0.f;
#pragma unroll
    for (int q = 0; q < 4; q++) {
        float4 v = row[lane + 32 * q];
        s  += v.x + v.y + v.z + v.w;
        sq += v.x * v.x + v.y * v.y + v.z * v.z + v.w * v.w;
        __half2 h0 = __floats2half2_rn(v.x, v.y);
        __half2 h1 = __floats2half2_rn(v.z, v.w);
        uint2 packed;
        packed.x = *reinterpret_cast<uint32_t*>(&h0);
        packed.y = *reinterpret_cast<uint32_t*>(&h1);
        hout[lane + 32 * q] = packed;
    }
#pragma unroll
    for (int off = 16; off > 0; off >>= 1) {
        s  += __shfl_xor_sync(0xffffffffu, s,  off);
        sq += __shfl_xor_sync(0xffffffffu, sq, off);
    }
    if (lane == 0) {
        g_q[warp] = sq - 2.f * EPSV * s;
        g_p[warp] = sq + 2.f * EPSV * s + (float)D_SZ * EPSV * EPSV;
        atomicAdd(&g_cnt[lab[warp]], 1);
    }
}

// ---------------------------------------------------------------------------
// Kernel 2: upper-triangle 128x128x512 gram tile, 4 warps, 64x64 warp tile,
// double-buffered fragments, dual-sided epilogue. (R9 mainloop, no tail.)
// ---------------------------------------------------------------------------
__global__ void __launch_bounds__(128, 2)
gemm_triplet_kernel(const int* __restrict__ lab) {
    extern __shared__ __align__(1024) char dsm[];
    __shared__ int   s_labi[128];
    __shared__ int   s_labj[128];
    __shared__ float s_qi[128];
    __shared__ float s_qj[128];
    __shared__ float hp_s[128][2];
    __shared__ float hn_s[128][2];
    __shared__ float hp_cs[128][2];
    __shared__ float hn_cs[128][2];

    // map linear block id -> upper-triangle (ti, tj), ti <= tj
    int bid = blockIdx.x;
    int ti = 0, rem = bid;
    while (rem >= NSPLIT - ti) { rem -= NSPLIT - ti; ti++; }
    const int tj = ti + rem;
    const bool diag = (ti == tj);

    const int tid  = threadIdx.x;
    const int wid  = tid >> 5, lane = tid & 31;
    const int wr   = wid >> 1, wc = wid & 1;        // 2 x 2 warp grid
    const int hl   = lane >> 4;
    const int l15  = lane & 15;
    const int i0   = ti * 128;
    const int j0   = tj * 128;
    const uint32_t smem = smem_u32(dsm);

    s_labi[tid] = lab[i0 + tid];
    s_labj[tid] = lab[j0 + tid];
    s_qi[tid]   = g_q[i0 + tid];
    s_qj[tid]   = g_q[j0 + tid];

    float d[4][8][4];
#pragma unroll
    for (int a = 0; a < 4; a++)
#pragma unroll
        for (int b = 0; b < 8; b++)
#pragma unroll
            for (int e = 0; e < 4; e++) d[a][b][e] = 0.f;

    load_stage(smem + 0 * STG, i0, j0, 0,  tid, diag); CP_COMMIT();
    load_stage(smem + 1 * STG, i0, j0, 64, tid, diag); CP_COMMIT();

#define LOAD_FRAGS(abuf, bbuf, ksv) do {                                          \
    _Pragma("unroll")                                                             \
    for (int mt = 0; mt < 4; mt++) {                                              \
        int arow = wr * 64 + mt * 16 + l15;                                       \
        uint32_t ad = As + arow * 128 +                                           \
                      (((((ksv) << 1) | hl) ^ (arow & 7)) << 4);                  \
        LDMATRIX_X4((abuf)[mt], ad);                                              \
    }                                                                             \
    _Pragma("unroll")                                                             \
    for (int np = 0; np < 4; np++) {                                              \
        int brow = wc * 64 + np * 16 + l15;                                       \
        uint32_t bd = Bs + brow * 128 +                                           \
                      (((((ksv) << 1) | hl) ^ (brow & 7)) << 4);                  \
        LDMATRIX_X4((bbuf)[np], bd);                                              \
    }                                                                             \
} while (0)

#define DO_MMA(abuf, bbuf) do {                                                   \
    _Pragma("unroll")                                                             \
    for (int np = 0; np < 4; np++)                                                \
        _Pragma("unroll")                                                         \
        for (int mt = 0; mt < 4; mt++) {                                          \
            MMA16816(d[mt][2 * np],     (abuf)[mt], (bbuf)[np][0], (bbuf)[np][2]);\
            MMA16816(d[mt][2 * np + 1], (abuf)[mt], (bbuf)[np][1], (bbuf)[np][3]);\
        }                                                                         \
} while (0)

#pragma unroll 1
    for (int c = 0; c < 8; c++) {
        if (c == 7) asm volatile("cp.async.wait_group 0;" ::: "memory");
        else        asm volatile("cp.async.wait_group 1;" ::: "memory");
        __syncthreads();
        if (c + 2 < 8) {
            load_stage(smem + ((c + 2) % 3) * STG, i0, j0, (c + 2) * 64, tid, diag);
            CP_COMMIT();
        }
        const uint32_t As = smem + (c % 3) * STG;
        const uint32_t Bs = diag ? As : (As + 16384);

        uint32_t af[2][4][4], bf[2][4][4];
        LOAD_FRAGS(af[0], bf[0], 0);
#pragma unroll
        for (int ks = 0; ks < 4; ks++) {
            if (ks < 3) LOAD_FRAGS(af[(ks + 1) & 1], bf[(ks + 1) & 1], ks + 1);
            DO_MMA(af[ks & 1], bf[ks & 1]);
        }
    }

    // ===== dual-sided epilogue =====
    float hpc[16], hnc[16];
#pragma unroll
    for (int k = 0; k < 16; k++) { hpc[k] = -BIGV; hnc[k] = BIGV; }

#pragma unroll
    for (int mt = 0; mt < 4; mt++) {
        int r0 = wr * 64 + mt * 16 + (lane >> 2);
        int li0 = s_labi[r0], li1 = s_labi[r0 + 8];
        float qi0 = s_qi[r0], qi1 = s_qi[r0 + 8];
        float hp0 = -BIGV, hp1 = -BIGV, hn0 = BIGV, hn1 = BIGV;
#pragma unroll
        for (int nt = 0; nt < 8; nt++) {
            int c0 = wc * 64 + nt * 8 + ((lane & 3) << 1);
            float q0 = s_qj[c0], q1 = s_qj[c0 + 1];
            int lj0 = s_labj[c0], lj1 = s_labj[c0 + 1];
            float g00 = d[mt][nt][0], g01 = d[mt][nt][1];
            float g10 = d[mt][nt][2], g11 = d[mt][nt][3];
            bool e00 = (li0 == lj0), e01 = (li0 == lj1);
            bool e10 = (li1 == lj0), e11 = (li1 == lj1);
            float m00 = fmaf(g00, -2.f, q0);
            float m01 = fmaf(g01, -2.f, q1);
            float m10 = fmaf(g10, -2.f, q0);
            float m11 = fmaf(g11, -2.f, q1);
            if (e00) hp0 = fmaxf(hp0, m00); else hn0 = fminf(hn0, m00);
            if (e01) hp0 = fmaxf(hp0, m01); else hn0 = fminf(hn0, m01);
            if (e10) hp1 = fmaxf(hp1, m10); else hn1 = fminf(hn1, m10);
            if (e11) hp1 = fmaxf(hp1, m11); else hn1 = fminf(hn1, m11);
            if (!diag) {
                float n00 = fmaf(g00, -2.f, qi0);
                float n01 = fmaf(g01, -2.f, qi0);
                float n10 = fmaf(g10, -2.f, qi1);
                float n11 = fmaf(g11, -2.f, qi1);
                int k0 = nt * 2, k1 = nt * 2 + 1;
                if (e00) hpc[k0] = fmaxf(hpc[k0], n00); else hnc[k0] = fminf(hnc[k0], n00);
                if (e10) hpc[k0] = fmaxf(hpc[k0], n10); else hnc[k0] = fminf(hnc[k0], n10);
                if (e01) hpc[k1] = fmaxf(hpc[k1], n01); else hnc[k1] = fminf(hnc[k1], n01);
                if (e11) hpc[k1] = fmaxf(hpc[k1], n11); else hnc[k1] = fminf(hnc[k1], n11);
            }
        }
#pragma unroll
        for (int off = 1; off < 4; off <<= 1) {
            hp0 = fmaxf(hp0, __shfl_xor_sync(0xffffffffu, hp0, off));
            hp1 = fmaxf(hp1, __shfl_xor_sync(0xffffffffu, hp1, off));
            hn0 = fminf(hn0, __shfl_xor_sync(0xffffffffu, hn0, off));
            hn1 = fminf(hn1, __shfl_xor_sync(0xffffffffu, hn1, off));
        }
        if ((lane & 3) == 0) {
            hp_s[r0][wc] = hp0; hp_s[r0 + 8][wc] = hp1;
            hn_s[r0][wc] = hn0; hn_s[r0 + 8][wc] = hn1;
        }
    }

    if (!diag) {
#pragma unroll
        for (int off = 4; off <= 16; off <<= 1) {
#pragma unroll
            for (int k = 0; k < 16; k++) {
                hpc[k] = fmaxf(hpc[k], __shfl_xor_sync(0xffffffffu, hpc[k], off));
                hnc[k] = fminf(hnc[k], __shfl_xor_sync(0xffffffffu, hnc[k], off));
            }
        }
        if ((lane >> 2) == 0) {
#pragma unroll
            for (int k = 0; k < 16; k++) {
                int col = wc * 64 + (k >> 1) * 8 + ((lane & 3) << 1) + (k & 1);
                hp_cs[col][wr] = hpc[k];
                hn_cs[col][wr] = hnc[k];
            }
        }
    }
    __syncthreads();
    {
        float hp = fmaxf(hp_s[tid][0], hp_s[tid][1]);
        float hn = fminf(hn_s[tid][0], hn_s[tid][1]);
        g_hp[tj][i0 + tid] = hp;
        g_hn[tj][i0 + tid] = hn;
        if (!diag) {
            float hpc2 = fmaxf(hp_cs[tid][0], hp_cs[tid][1]);
            float hnc2 = fminf(hn_cs[tid][0], hn_cs[tid][1]);
            g_hp[ti][j0 + tid] = hpc2;
            g_hn[ti][j0 + tid] = hnc2;
        }
    }
}

// ---------------------------------------------------------------------------
// Kernel 3: parallel combine — warp per 4 anchors, lane = split.
// 128 CTAs x 256 threads; last CTA does final reduce + counter resets.
// ---------------------------------------------------------------------------
__global__ void combine_kernel(const int* __restrict__ lab, float* __restrict__ out) {
    __shared__ float s_sum[8], s_cn[8];
    __shared__ int   s_last;
    const int tid = threadIdx.x, wid = tid >> 5, lane = tid & 31;
    const int gw  = blockIdx.x * 8 + wid;      // 0..1023
    const int a0  = gw * 4;                    // 4 contiguous anchors per warp

    // lane = split index; float4 spans the 4 anchors (coalesced 16B per lane)
    float4 hp4 = *reinterpret_cast<const float4*>(&g_hp[lane][a0]);
    float4 hn4 = *reinterpret_cast<const float4*>(&g_hn[lane][a0]);
#pragma unroll
    for (int off = 16; off > 0; off >>= 1) {
        hp4.x = fmaxf(hp4.x, __shfl_xor_sync(0xffffffffu, hp4.x, off));
        hp4.y = fmaxf(hp4.y, __shfl_xor_sync(0xffffffffu, hp4.y, off));
        hp4.z = fmaxf(hp4.z, __shfl_xor_sync(0xffffffffu, hp4.z, off));
        hp4.w = fmaxf(hp4.w, __shfl_xor_sync(0xffffffffu, hp4.w, off));
        hn4.x = fminf(hn4.x, __shfl_xor_sync(0xffffffffu, hn4.x, off));
        hn4.y = fminf(hn4.y, __shfl_xor_sync(0xffffffffu, hn4.y, off));
        hn4.z = fminf(hn4.z, __shfl_xor_sync(0xffffffffu, hn4.z, off));
        hn4.w = fminf(hn4.w, __shfl_xor_sync(0xffffffffu, hn4.w, off));
    }

    float lsum = 0.f, lcnt = 0.f;
    if (lane < 4) {
        float hp = (lane == 0) ? hp4.x : (lane == 1) ? hp4.y : (lane == 2) ? hp4.z : hp4.w;
        float hn = (lane == 0) ? hn4.x : (lane == 1) ? hn4.y : (lane == 2) ? hn4.z : hn4.w;
        int a = a0 + lane;
        int k = g_cnt[lab[a]];
        bool valid = (k >= 2) && (k < B_SZ);
        float p = g_p[a];
        float dp = sqrtf(fmaxf(p + hp, 0.f));
        float dn = sqrtf(fmaxf(p + hn, 0.f));
        float v = dp - dn + MARGIN;
        if (valid) { lsum = (v > 0.f) ? v : 0.f; lcnt = 1.f; }
    }
#pragma unroll
    for (int off = 1; off < 4; off <<= 1) {
        lsum += __shfl_xor_sync(0xffffffffu, lsum, off);
        lcnt += __shfl_xor_sync(0xffffffffu, lcnt, off);
    }
    if (lane == 0) { s_sum[wid] = lsum; s_cn[wid] = lcnt; }
    __syncthreads();
    if (tid == 0) {
        float bs = 0.f, bc = 0.f;
#pragma unroll
        for (int w = 0; w < 8; w++) { bs += s_sum[w]; bc += s_cn[w]; }
        g_psum[blockIdx.x] = bs;
        g_pcnt[blockIdx.x] = bc;
        __threadfence();
        unsigned old = atomicAdd(&g_done, 1u);
        s_last = (old == CCTA - 1) ? 1 : 0;
    }
    __syncthreads();
    if (s_last) {
        __threadfence();
        if (wid == 0) {
            float fs = 0.f, fc = 0.f;
#pragma unroll
            for (int r = 0; r < 4; r++) {
                fs += g_psum[lane + r * 32];
                fc += g_pcnt[lane + r * 32];
            }
#pragma unroll
            for (int off = 16; off > 0; off >>= 1) {
                fs += __shfl_xor_sync(0xffffffffu, fs, off);
                fc += __shfl_xor_sync(0xffffffffu, fc, off);
            }
            if (lane == 0) out[0] = (fc > 0.f) ? (fs / fc) : 0.f;
        }
        // reset scratch counters for next graph replay
        for (int i = tid; i < 512; i += 256) g_cnt[i] = 0;
        if (tid == 0) { g_done = 0; __threadfence(); }
    }
}

// ---------------------------------------------------------------------------
extern "C" void kernel_launch(void* const* d_in, const int* in_sizes, int n_in,
                              void* d_out, int out_size) {
    const float* E   = (const float*)d_in[0];
    const int*   lab = (const int*)d_in[1];
    float*       out = (float*)d_out;
    (void)in_sizes; (void)n_in; (void)out_size;

    cudaFuncSetAttribute(gemm_triplet_kernel,
                         cudaFuncAttributeMaxDynamicSharedMemorySize, DYN_SMEM);

    prep_stats_kernel<<<B_SZ / 8, 256>>>(E, lab);
    gemm_triplet_kernel<<<NTILES, 128, DYN_SMEM>>>(lab);
    combine_kernel<<<CCTA, 256>>>(lab, out);
}